// round 6
// baseline (speedup 1.0000x reference)
#include <cuda_runtime.h>
#include <cuda_bf16.h>

// out[t,b,i,e] = x[t,b,i] * W[i,e] + b[e]
// T=8, B=64, D=512, E=256 -> 67,108,864 fp32 outputs (268 MB). Store-BW bound.
//
// Mapping: one warp handles ROWS_PER_WARP=4 consecutive output rows.
// E = 256 floats = 64 float4; each lane writes float4 #lane and #(lane+32)
// of each row -> 8 independent STG.128 per thread (deep store window).
// x loads are uniform warp broadcasts; W rows (1 KB each) and b stay L2-hot.
// __stcs streaming stores keep the 268 MB write stream from evicting them.

#define D_DIM  512
#define E4     64                        // float4 per row
#define NROWS  (8 * 64 * 512)            // 262144 rows
#define ROWS_PER_WARP 4
#define WARPS_PER_BLOCK 8
#define THREADS (WARPS_PER_BLOCK * 32)
#define NBLOCKS (NROWS / (ROWS_PER_WARP * WARPS_PER_BLOCK))   // 8192

__global__ __launch_bounds__(THREADS)
void dense_embed_kernel(const float* __restrict__ x,
                        const float4* __restrict__ W4,
                        const float4* __restrict__ b4,
                        float4* __restrict__ out)
{
    unsigned warp_id = blockIdx.x * WARPS_PER_BLOCK + (threadIdx.x >> 5);
    unsigned lane    = threadIdx.x & 31;
    unsigned row0    = warp_id * ROWS_PER_WARP;

    unsigned c0 = lane;
    unsigned c1 = lane + 32;

    float4 bb0 = __ldg(&b4[c0]);
    float4 bb1 = __ldg(&b4[c1]);

    // Batch all loads first (front-batched MLP), then all stores.
    float  xv[ROWS_PER_WARP];
    float4 w0[ROWS_PER_WARP], w1[ROWS_PER_WARP];

    #pragma unroll
    for (int r = 0; r < ROWS_PER_WARP; ++r) {
        unsigned row = row0 + r;
        unsigned i   = row & (D_DIM - 1);        // row % 512
        xv[r] = __ldg(&x[row]);                  // uniform broadcast
        const float4* Wrow = W4 + (i << 6);
        w0[r] = __ldg(&Wrow[c0]);
        w1[r] = __ldg(&Wrow[c1]);
    }

    #pragma unroll
    for (int r = 0; r < ROWS_PER_WARP; ++r) {
        float4 o0, o1;
        o0.x = fmaf(xv[r], w0[r].x, bb0.x);
        o0.y = fmaf(xv[r], w0[r].y, bb0.y);
        o0.z = fmaf(xv[r], w0[r].z, bb0.z);
        o0.w = fmaf(xv[r], w0[r].w, bb0.w);
        o1.x = fmaf(xv[r], w1[r].x, bb1.x);
        o1.y = fmaf(xv[r], w1[r].y, bb1.y);
        o1.z = fmaf(xv[r], w1[r].z, bb1.z);
        o1.w = fmaf(xv[r], w1[r].w, bb1.w);

        float4* orow = out + ((unsigned long long)(row0 + r) << 6);
        __stcs(&orow[c0], o0);
        __stcs(&orow[c1], o1);
    }
}

extern "C" void kernel_launch(void* const* d_in, const int* in_sizes, int n_in,
                              void* d_out, int out_size)
{
    const float*  x  = (const float*)d_in[0];
    const float4* W4 = (const float4*)d_in[1];
    const float4* b4 = (const float4*)d_in[2];
    float4* out = (float4*)d_out;

    dense_embed_kernel<<<NBLOCKS, THREADS>>>(x, W4, b4, out);
}